// round 6
// baseline (speedup 1.0000x reference)
#include <cuda_runtime.h>

#define BB 256
#define CC 700
#define TT 500
#define NN 512
#define OO 20
#define CP 704
#define NCTAS 128
#define NTH 256
#define NGRP 8
#define GSZ 16

// dyn smem: sWr2[512*32], sW2[512*32], sWr3[512*32], Ws[128*32] (floats),
// then smA/B/C[512] (unsigned)
#define MAT_F (512 * 32)
#define WS_F (128 * 32)
#define SMEM_BYTES ((3 * MAT_F + WS_F) * 4 + 3 * 512 * 4)

__device__ float g_W1t[(size_t)CP * NN];
__device__ float g_Wr2t[(size_t)NN * NN];
__device__ float g_W2t[(size_t)NN * NN];
__device__ float g_W3t[(size_t)NN * NN];
__device__ float g_Wr3t[(size_t)NN * NN];
__device__ float g_W4t[(size_t)NN * OO];
__device__ float g_H1[(size_t)TT * BB * NN];
__device__ unsigned g_sp[3][2][BB * 16];
__device__ unsigned g_flag[3][NGRP][GSZ];   // producer epoch flags

// consumer-side wait: lane l polls producer l's epoch flag for (layer, group)
__device__ __forceinline__ void wait_flags(int layer, int bt, unsigned epoch, int tid) {
    if (tid < GSZ) {
        volatile unsigned* f = &g_flag[layer][bt][tid];
        while (*f < epoch) {}
    }
    __threadfence();
    __syncthreads();
}

__global__ void prep_kernel(
    const float* __restrict__ W1, const float* __restrict__ W2,
    const float* __restrict__ Wr2, const float* __restrict__ W3,
    const float* __restrict__ Wr3, const float* __restrict__ W4)
{
    const int tid = blockIdx.x * blockDim.x + threadIdx.x;
    const int str = gridDim.x * blockDim.x;
    for (int i = tid; i < CP * NN; i += str) {
        int c = i >> 9, n = i & 511;
        g_W1t[i] = (c < CC) ? W1[(size_t)n * CC + c] : 0.f;
    }
    for (int i = tid; i < NN * NN; i += str) {
        int k = i >> 9, n = i & 511;
        size_t j = (size_t)n * NN + k;
        g_Wr2t[i] = Wr2[j]; g_W2t[i] = W2[j]; g_W3t[i] = W3[j]; g_Wr3t[i] = Wr3[j];
    }
    for (int i = tid; i < NN * OO; i += str)
        g_W4t[i] = W4[(size_t)(i % OO) * NN + (i / OO)];
    for (int i = tid; i < 3 * 2 * BB * 16; i += str) (&g_sp[0][0][0])[i] = 0u;
    for (int i = tid; i < 3 * NGRP * GSZ; i += str) (&g_flag[0][0][0])[i] = 0u;
}

// H1[t][b][n] = sum_c x[b][c][t] * W1[n][c]  (ascending-c FFMA chain)
__global__ __launch_bounds__(256, 2) void h1_gemm_kernel(const float* __restrict__ x)
{
    __shared__ float As[8][128], Bs[8][128];
    const int n0 = blockIdx.x * 128, t0 = blockIdx.y * 128, b = blockIdx.z;
    const int tx = threadIdx.x & 15, ty = threadIdx.x >> 4;
    const float* __restrict__ xb = x + (size_t)b * CC * TT;
    float acc[8][8] = {};
    float ra[4], rb[4];

#define H1_LOAD(c0)                                                          \
    _Pragma("unroll")                                                        \
    for (int u = 0; u < 4; ++u) {                                            \
        int i = threadIdx.x + u * 256, kc = i >> 7, e = i & 127;             \
        int c = (c0) + kc, t = t0 + e;                                       \
        ra[u] = (c < CC && t < TT) ? xb[(size_t)c * TT + t] : 0.f;           \
        rb[u] = g_W1t[(size_t)c * NN + n0 + e];                              \
    }

    H1_LOAD(0)
    for (int c0 = 0; c0 < CP; c0 += 8) {
#pragma unroll
        for (int u = 0; u < 4; ++u) {
            int i = threadIdx.x + u * 256;
            As[i >> 7][i & 127] = ra[u];
            Bs[i >> 7][i & 127] = rb[u];
        }
        __syncthreads();
        if (c0 + 8 < CP) { H1_LOAD(c0 + 8) }
#pragma unroll
        for (int kc = 0; kc < 8; ++kc) {
            float av[8], bv[8];
            *(float4*)av       = *(const float4*)&As[kc][ty * 8];
            *(float4*)(av + 4) = *(const float4*)&As[kc][ty * 8 + 4];
            *(float4*)bv       = *(const float4*)&Bs[kc][tx * 8];
            *(float4*)(bv + 4) = *(const float4*)&Bs[kc][tx * 8 + 4];
#pragma unroll
            for (int i = 0; i < 8; ++i)
#pragma unroll
                for (int j = 0; j < 8; ++j)
                    acc[i][j] = __fmaf_rn(av[i], bv[j], acc[i][j]);
        }
        __syncthreads();
    }
#pragma unroll
    for (int i = 0; i < 8; ++i) {
        int t = t0 + ty * 8 + i;
        if (t < TT) {
            float* dst = &g_H1[((size_t)t * BB + b) * NN + n0 + tx * 8];
            *(float4*)dst       = *(float4*)&acc[i][0];
            *(float4*)(dst + 4) = *(float4*)&acc[i][4];
        }
    }
}

// resident gather (weights in smem, stride 32), ascending k; optional dual mask
template <bool DUAL>
__device__ __forceinline__ void gather_res(
    const float* __restrict__ sW, const unsigned* __restrict__ smX,
    const unsigned* __restrict__ smY, int bl, int nl, float* aX, float* aY)
{
#pragma unroll 1
    for (int w = 0; w < 16; ++w) {
        const float* base = sW + (w * 32) * 32 + nl;
        unsigned m = smX[bl * 16 + w];
        while (m) {
            int j = __ffs(m) - 1; m &= m - 1u;
            const float4 wv = *(const float4*)(base + j * 32);
            aX[0] = __fadd_rn(aX[0], wv.x); aX[1] = __fadd_rn(aX[1], wv.y);
            aX[2] = __fadd_rn(aX[2], wv.z); aX[3] = __fadd_rn(aX[3], wv.w);
        }
        if (DUAL) {
            unsigned my = smY[bl * 16 + w];
            while (my) {
                int j = __ffs(my) - 1; my &= my - 1u;
                const float4 wv = *(const float4*)(base + j * 32);
                aY[0] = __fadd_rn(aY[0], wv.x); aY[1] = __fadd_rn(aY[1], wv.y);
                aY[2] = __fadd_rn(aY[2], wv.z); aY[3] = __fadd_rn(aY[3], wv.w);
            }
        }
    }
}

// staged gather (W3 streamed through Ws in 128-k chunks), ascending k
__device__ __forceinline__ void gather_staged(
    const float* __restrict__ Wt, const unsigned* __restrict__ smX,
    float* __restrict__ Ws, int bl, int nl, int n0, int tid, float* aX)
{
#pragma unroll 1
    for (int kc = 0; kc < 4; ++kc) {
        const float* __restrict__ src = Wt + (size_t)(kc * 128) * NN + n0;
#pragma unroll
        for (int u = 0; u < 4; ++u) {
            int idx = tid + u * 256;                     // float4 index
            int row = idx >> 3, c4 = idx & 7;
            ((float4*)Ws)[idx] = *(const float4*)(src + (size_t)row * NN + c4 * 4);
        }
        __syncthreads();
#pragma unroll
        for (int w = 0; w < 4; ++w) {
            unsigned m = smX[bl * 16 + kc * 4 + w];
            while (m) {
                int j = __ffs(m) - 1; m &= m - 1u;
                const float4 wv = *(const float4*)(Ws + (w * 32 + j) * 32 + nl);
                aX[0] = __fadd_rn(aX[0], wv.x); aX[1] = __fadd_rn(aX[1], wv.y);
                aX[2] = __fadd_rn(aX[2], wv.z); aX[3] = __fadd_rn(aX[3], wv.w);
            }
        }
        __syncthreads();
    }
}

// LIF: m = ((tau*m)*(1-s))+h, separate roundings
__device__ __forceinline__ unsigned lif4(float* m, const float* tau, const float* vth,
                                         const float* h, float* s, float* cnt)
{
    unsigned nib = 0u;
#pragma unroll
    for (int j = 0; j < 4; ++j) {
        float one_ms = __fadd_rn(1.f, -s[j]);
        m[j] = __fadd_rn(__fmul_rn(__fmul_rn(tau[j], m[j]), one_ms), h[j]);
        float sp = (__fadd_rn(m[j], -vth[j]) > 0.f) ? 1.f : 0.f;
        cnt[j] += sp; s[j] = sp;
        nib |= ((unsigned)sp) << j;
    }
    return nib;
}

// pack 8 nibbles -> 32-bit row word via shuffle-OR, publish + epoch flag
__device__ __forceinline__ void publish(int layer, int parw, int bt, int ns,
                                        int b0, int bl, int nq, int tid,
                                        unsigned nib, unsigned epoch)
{
    unsigned word = nib << (nq * 4);
    word |= __shfl_xor_sync(0xffffffffu, word, 1);
    word |= __shfl_xor_sync(0xffffffffu, word, 2);
    word |= __shfl_xor_sync(0xffffffffu, word, 4);
    if (nq == 0) g_sp[layer][parw][(b0 + bl) * 16 + ns] = word;
    __syncthreads();
    if (tid == 0) { __threadfence(); g_flag[layer][bt][ns] = epoch; }
}

__global__ __launch_bounds__(NTH, 1) void rsnn_recurrent_kernel(
    float* __restrict__ out,
    const float* __restrict__ b1, const float* __restrict__ br2,
    const float* __restrict__ b2, const float* __restrict__ b3,
    const float* __restrict__ br3, const float* __restrict__ b4,
    const float* __restrict__ Vth1, const float* __restrict__ tau1,
    const float* __restrict__ Vth2, const float* __restrict__ tau2,
    const float* __restrict__ Vth3, const float* __restrict__ tau3)
{
    extern __shared__ float dyn[];
    float* sWr2 = dyn;
    float* sW2  = dyn + MAT_F;
    float* sWr3 = dyn + 2 * MAT_F;
    float* Ws   = dyn + 3 * MAT_F;
    unsigned* smA = (unsigned*)(dyn + 3 * MAT_F + WS_F);
    unsigned* smB = smA + 512;
    unsigned* smC = smB + 512;

    const int tid = threadIdx.x;
    const int bt = blockIdx.x >> 4, ns = blockIdx.x & 15;
    const int b0 = bt * 32, n0 = ns * 32;
    const int bl = tid >> 3, nq = tid & 7, nl = nq * 4;
    const int b = b0 + bl, n = n0 + nl;

    // resident weight slices
    for (int i = tid; i < 512 * 32; i += NTH) {
        int r = i >> 5, c = i & 31;
        sWr2[i] = g_Wr2t[(size_t)r * NN + n0 + c];
        sW2 [i] = g_W2t [(size_t)r * NN + n0 + c];
        sWr3[i] = g_Wr3t[(size_t)r * NN + n0 + c];
    }

    float ta1[4], ta2[4], ta3[4], vt1[4], vt2[4], vt3[4];
    float bb1[4], bb2[4], bb3[4], br2v[4], br3v[4];
    *(float4*)ta1 = *(const float4*)(tau1 + n); *(float4*)vt1 = *(const float4*)(Vth1 + n);
    *(float4*)ta2 = *(const float4*)(tau2 + n); *(float4*)vt2 = *(const float4*)(Vth2 + n);
    *(float4*)ta3 = *(const float4*)(tau3 + n); *(float4*)vt3 = *(const float4*)(Vth3 + n);
    *(float4*)bb1 = *(const float4*)(b1 + n);   *(float4*)bb2 = *(const float4*)(b2 + n);
    *(float4*)bb3 = *(const float4*)(b3 + n);
    *(float4*)br2v = *(const float4*)(br2 + n); *(float4*)br3v = *(const float4*)(br3 + n);

    float m1[4] = {}, m2[4] = {}, m3[4] = {};
    float s1[4] = {}, s2[4] = {}, s3[4] = {};
    float c1[4] = {}, c2[4] = {}, c3[4] = {};
    float r2[4], r3[4];
    __syncthreads();

    for (int t = 0; t <= TT; ++t) {
        const int parw = t & 1, parr = parw ^ 1;

        // prefetch H1 (no spike dependency)
        float4 h1v = {0.f, 0.f, 0.f, 0.f};
        if (t < TT) h1v = *(const float4*)&g_H1[((size_t)t * BB + b) * NN + n];

        // need s3(t-1) from all group producers (s1/s2 flags observed last step)
        wait_flags(2, bt, (unsigned)t, tid);
        for (int i = tid; i < 512; i += NTH) {
            int gi = (b0 + (i >> 4)) * 16 + (i & 15);
            smA[i] = g_sp[0][parr][gi];
            smB[i] = g_sp[1][parr][gi];
            smC[i] = g_sp[2][parr][gi];
        }
        __syncthreads();

        // output for step t-1 (warps 0-1; overlaps with other warps' gathers):
        // dense ascending-k select chain == reference fp32 chain, then +b4
        if (t > 0 && tid < 40) {
            int p = ns * 40 + tid;
            int bb = p / OO, o = p % OO;
            float acc = 0.f;
#pragma unroll 1
            for (int w = 0; w < 16; ++w) {
                unsigned word = smC[bb * 16 + w];
#pragma unroll
                for (int j = 0; j < 32; ++j) {
                    float sel = (word & (1u << j)) ? g_W4t[(w * 32 + j) * OO + o] : 0.f;
                    acc = __fadd_rn(acc, sel);
                }
            }
            out[((size_t)(b0 + bb) * OO + o) * TT + (t - 1)] = __fadd_rn(acc, b4[o]);
        }
        if (t == TT) break;

        // Phase 1: r1 = Wr2.s1p, r2 = Wr2.s2p (dual), r3 = Wr3.s3p (all resident)
        float r1[4] = {};
        r2[0] = r2[1] = r2[2] = r2[3] = 0.f;
        r3[0] = r3[1] = r3[2] = r3[3] = 0.f;
        gather_res<true >(sWr2, smA, smB, bl, nl, r1, r2);
        gather_res<false>(sWr3, smC, smC, bl, nl, r3, r3);

        float h[4];
        const float d1[4] = {h1v.x, h1v.y, h1v.z, h1v.w};
#pragma unroll
        for (int j = 0; j < 4; ++j)   // ((d1 + b1) + r1) + br2
            h[j] = __fadd_rn(__fadd_rn(__fadd_rn(d1[j], bb1[j]), r1[j]), br2v[j]);
        unsigned nib = lif4(m1, ta1, vt1, h, s1, c1);
        publish(0, parw, bt, ns, b0, bl, nq, tid, nib, (unsigned)(t + 1));

        // Phase 2: a2 = W2.s1(t) (resident)
        wait_flags(0, bt, (unsigned)(t + 1), tid);
        for (int i = tid; i < 512; i += NTH)
            smA[i] = g_sp[0][parw][(b0 + (i >> 4)) * 16 + (i & 15)];
        __syncthreads();
        float a2[4] = {};
        gather_res<false>(sW2, smA, smA, bl, nl, a2, a2);
#pragma unroll
        for (int j = 0; j < 4; ++j)
            h[j] = __fadd_rn(__fadd_rn(__fadd_rn(a2[j], bb2[j]), r2[j]), br2v[j]);
        nib = lif4(m2, ta2, vt2, h, s2, c2);
        publish(1, parw, bt, ns, b0, bl, nq, tid, nib, (unsigned)(t + 1));

        // Phase 3: a3 = W3.s2(t) (staged)
        wait_flags(1, bt, (unsigned)(t + 1), tid);
        for (int i = tid; i < 512; i += NTH)
            smB[i] = g_sp[1][parw][(b0 + (i >> 4)) * 16 + (i & 15)];
        __syncthreads();
        float a3[4] = {};
        gather_staged(g_W3t, smB, Ws, bl, nl, n0, tid, a3);
#pragma unroll
        for (int j = 0; j < 4; ++j)
            h[j] = __fadd_rn(__fadd_rn(__fadd_rn(a3[j], bb3[j]), r3[j]), br3v[j]);
        nib = lif4(m3, ta3, vt3, h, s3, c3);
        publish(2, parw, bt, ns, b0, bl, nq, tid, nib, (unsigned)(t + 1));
    }

    const float iT = 1.f / (float)TT;
    const size_t base = (size_t)BB * OO * TT, off = (size_t)b * NN + n;
#pragma unroll
    for (int j = 0; j < 4; ++j) {
        out[base + off + j]                       = __fmul_rn(c1[j], iT);
        out[base + (size_t)BB * NN + off + j]     = __fmul_rn(c2[j], iT);
        out[base + 2 * (size_t)BB * NN + off + j] = __fmul_rn(c3[j], iT);
    }
}

extern "C" void kernel_launch(void* const* d_in, const int* in_sizes, int n_in,
                              void* d_out, int out_size)
{
    const float* x   = (const float*)d_in[0];
    const float* W1  = (const float*)d_in[1];
    const float* b1  = (const float*)d_in[2];
    const float* W2  = (const float*)d_in[3];
    const float* b2  = (const float*)d_in[4];
    const float* Wr2 = (const float*)d_in[5];
    const float* br2 = (const float*)d_in[6];
    const float* W3  = (const float*)d_in[7];
    const float* b3  = (const float*)d_in[8];
    const float* Wr3 = (const float*)d_in[9];
    const float* br3 = (const float*)d_in[10];
    const float* W4  = (const float*)d_in[11];
    const float* b4  = (const float*)d_in[12];
    const float* Vth1 = (const float*)d_in[13];
    const float* tau1 = (const float*)d_in[14];
    const float* Vth2 = (const float*)d_in[15];
    const float* tau2 = (const float*)d_in[16];
    const float* Vth3 = (const float*)d_in[17];
    const float* tau3 = (const float*)d_in[18];
    float* out = (float*)d_out;

    cudaFuncSetAttribute(rsnn_recurrent_kernel,
                         cudaFuncAttributeMaxDynamicSharedMemorySize, SMEM_BYTES);

    prep_kernel<<<256, 256>>>(W1, W2, Wr2, W3, Wr3, W4);
    dim3 g(NN / 128, 4, BB);
    h1_gemm_kernel<<<g, 256>>>(x);
    rsnn_recurrent_kernel<<<NCTAS, NTH, SMEM_BYTES>>>(
        out, b1, br2, b2, b3, br3, b4, Vth1, tau1, Vth2, tau2, Vth3, tau3);
}

// round 10
// speedup vs baseline: 1.4904x; 1.4904x over previous
#include <cuda_runtime.h>

#define BB 256
#define CC 700
#define TT 500
#define NN 512
#define OO 20
#define CP 704
#define NCTAS 128
#define NTH 512
#define NGRP 8
#define GSZ 16

// dyn smem: sWr2[512*32], sW2[512*32], sWr3[512*32], Ws[128*32] (floats),
// then smA/B/C[512] (unsigned)
#define MAT_F (512 * 32)
#define WS_F (128 * 32)
#define SMEM_BYTES ((3 * MAT_F + WS_F) * 4 + 3 * 512 * 4)

__device__ float g_W1t[(size_t)CP * NN];
__device__ float g_Wr2t[(size_t)NN * NN];
__device__ float g_W2t[(size_t)NN * NN];
__device__ float g_W3t[(size_t)NN * NN];
__device__ float g_Wr3t[(size_t)NN * NN];
__device__ float g_W4t[(size_t)NN * OO];
__device__ float g_H1[(size_t)TT * BB * NN];
__device__ unsigned g_sp[2][2][BB * 16];          // s1, s2 (double-buffered)
__device__ unsigned g_sp3[TT + 1][BB * 16];       // s3 per timestep (for out kernel)
__device__ unsigned g_gcnt[NGRP * 32];
__device__ volatile unsigned g_gphz[NGRP * 32];

__device__ __forceinline__ void group_barrier(int bt) {
    __threadfence();
    __syncthreads();
    if (threadIdx.x == 0) {
        const int gi = bt * 32;
        unsigned gen = g_gphz[gi];
        if (atomicAdd(&g_gcnt[gi], 1u) == GSZ - 1) {
            g_gcnt[gi] = 0u;
            __threadfence();
            g_gphz[gi] = gen + 1u;
        } else {
            while (g_gphz[gi] == gen) __nanosleep(32);
        }
        __threadfence();
    }
    __syncthreads();
}

__global__ void prep_kernel(
    const float* __restrict__ W1, const float* __restrict__ W2,
    const float* __restrict__ Wr2, const float* __restrict__ W3,
    const float* __restrict__ Wr3, const float* __restrict__ W4)
{
    const int tid = blockIdx.x * blockDim.x + threadIdx.x;
    const int str = gridDim.x * blockDim.x;
    for (int i = tid; i < CP * NN; i += str) {
        int c = i >> 9, n = i & 511;
        g_W1t[i] = (c < CC) ? W1[(size_t)n * CC + c] : 0.f;
    }
    for (int i = tid; i < NN * NN; i += str) {
        int k = i >> 9, n = i & 511;
        size_t j = (size_t)n * NN + k;
        g_Wr2t[i] = Wr2[j]; g_W2t[i] = W2[j]; g_W3t[i] = W3[j]; g_Wr3t[i] = Wr3[j];
    }
    for (int i = tid; i < NN * OO; i += str)
        g_W4t[i] = W4[(size_t)(i % OO) * NN + (i / OO)];
    for (int i = tid; i < 2 * 2 * BB * 16; i += str) (&g_sp[0][0][0])[i] = 0u;
    for (int i = tid; i < BB * 16; i += str) g_sp3[0][i] = 0u;   // s3(-1) = 0
    for (int i = tid; i < NGRP * 32; i += str) { g_gcnt[i] = 0u; g_gphz[i] = 0u; }
}

// H1[t][b][n] = sum_c x[b][c][t] * W1[n][c]  (ascending-c FFMA chain)
__global__ __launch_bounds__(256, 2) void h1_gemm_kernel(const float* __restrict__ x)
{
    __shared__ float As[8][128], Bs[8][128];
    const int n0 = blockIdx.x * 128, t0 = blockIdx.y * 128, b = blockIdx.z;
    const int tx = threadIdx.x & 15, ty = threadIdx.x >> 4;
    const float* __restrict__ xb = x + (size_t)b * CC * TT;
    float acc[8][8] = {};
    float ra[4], rb[4];

#define H1_LOAD(c0)                                                          \
    _Pragma("unroll")                                                        \
    for (int u = 0; u < 4; ++u) {                                            \
        int i = threadIdx.x + u * 256, kc = i >> 7, e = i & 127;             \
        int c = (c0) + kc, t = t0 + e;                                       \
        ra[u] = (c < CC && t < TT) ? xb[(size_t)c * TT + t] : 0.f;           \
        rb[u] = g_W1t[(size_t)c * NN + n0 + e];                              \
    }

    H1_LOAD(0)
    for (int c0 = 0; c0 < CP; c0 += 8) {
#pragma unroll
        for (int u = 0; u < 4; ++u) {
            int i = threadIdx.x + u * 256;
            As[i >> 7][i & 127] = ra[u];
            Bs[i >> 7][i & 127] = rb[u];
        }
        __syncthreads();
        if (c0 + 8 < CP) { H1_LOAD(c0 + 8) }
#pragma unroll
        for (int kc = 0; kc < 8; ++kc) {
            float av[8], bv[8];
            *(float4*)av       = *(const float4*)&As[kc][ty * 8];
            *(float4*)(av + 4) = *(const float4*)&As[kc][ty * 8 + 4];
            *(float4*)bv       = *(const float4*)&Bs[kc][tx * 8];
            *(float4*)(bv + 4) = *(const float4*)&Bs[kc][tx * 8 + 4];
#pragma unroll
            for (int i = 0; i < 8; ++i)
#pragma unroll
                for (int j = 0; j < 8; ++j)
                    acc[i][j] = __fmaf_rn(av[i], bv[j], acc[i][j]);
        }
        __syncthreads();
    }
#pragma unroll
    for (int i = 0; i < 8; ++i) {
        int t = t0 + ty * 8 + i;
        if (t < TT) {
            float* dst = &g_H1[((size_t)t * BB + b) * NN + n0 + tx * 8];
            *(float4*)dst       = *(float4*)&acc[i][0];
            *(float4*)(dst + 4) = *(float4*)&acc[i][4];
        }
    }
}

// resident gather, 2-wide per thread (float2), ascending k; optional dual mask
template <bool DUAL>
__device__ __forceinline__ void gather_res2(
    const float* __restrict__ sW, const unsigned* __restrict__ smX,
    const unsigned* __restrict__ smY, int bl, int nn2, float* aX, float* aY)
{
#pragma unroll 1
    for (int w = 0; w < 16; ++w) {
        const float* base = sW + (w * 32) * 32 + nn2;
        unsigned m = smX[bl * 16 + w];
        while (m) {
            int j = __ffs(m) - 1; m &= m - 1u;
            const float2 wv = *(const float2*)(base + j * 32);
            aX[0] = __fadd_rn(aX[0], wv.x); aX[1] = __fadd_rn(aX[1], wv.y);
        }
        if (DUAL) {
            unsigned my = smY[bl * 16 + w];
            while (my) {
                int j = __ffs(my) - 1; my &= my - 1u;
                const float2 wv = *(const float2*)(base + j * 32);
                aY[0] = __fadd_rn(aY[0], wv.x); aY[1] = __fadd_rn(aY[1], wv.y);
            }
        }
    }
}

// staged gather (W3 streamed through Ws in 128-k chunks), 2-wide, ascending k
__device__ __forceinline__ void gather_staged2(
    const float* __restrict__ Wt, const unsigned* __restrict__ smX,
    float* __restrict__ Ws, int bl, int nn2, int n0, int tid, float* aX)
{
#pragma unroll 1
    for (int kc = 0; kc < 4; ++kc) {
        const float* __restrict__ src = Wt + (size_t)(kc * 128) * NN + n0;
#pragma unroll
        for (int u = 0; u < 2; ++u) {
            int idx = tid + u * NTH;                     // float4 index, 1024 total
            int row = idx >> 3, c4 = idx & 7;
            ((float4*)Ws)[idx] = *(const float4*)(src + (size_t)row * NN + c4 * 4);
        }
        __syncthreads();
#pragma unroll
        for (int w = 0; w < 4; ++w) {
            unsigned m = smX[bl * 16 + kc * 4 + w];
            while (m) {
                int j = __ffs(m) - 1; m &= m - 1u;
                const float2 wv = *(const float2*)(Ws + (w * 32 + j) * 32 + nn2);
                aX[0] = __fadd_rn(aX[0], wv.x); aX[1] = __fadd_rn(aX[1], wv.y);
            }
        }
        __syncthreads();
    }
}

// LIF over 2 components: m = ((tau*m)*(1-s))+h, separate roundings
__device__ __forceinline__ unsigned lif2(float* m, const float* tau, const float* vth,
                                         const float* h, float* s, float* cnt)
{
    unsigned bits = 0u;
#pragma unroll
    for (int j = 0; j < 2; ++j) {
        float one_ms = __fadd_rn(1.f, -s[j]);
        m[j] = __fadd_rn(__fmul_rn(__fmul_rn(tau[j], m[j]), one_ms), h[j]);
        float sp = (__fadd_rn(m[j], -vth[j]) > 0.f) ? 1.f : 0.f;
        cnt[j] += sp; s[j] = sp;
        bits |= ((unsigned)sp) << j;
    }
    return bits;
}

// pack 16 threads x 2 bits -> 32-bit row word via shuffle-OR (stays in half-warp)
__device__ __forceinline__ void publish(unsigned* dst, int b0, int bl, int nh,
                                        unsigned bits)
{
    unsigned word = bits << (nh * 2);
    word |= __shfl_xor_sync(0xffffffffu, word, 1);
    word |= __shfl_xor_sync(0xffffffffu, word, 2);
    word |= __shfl_xor_sync(0xffffffffu, word, 4);
    word |= __shfl_xor_sync(0xffffffffu, word, 8);
    if (nh == 0) *dst = word;
}

__global__ __launch_bounds__(NTH, 1) void rsnn_recurrent_kernel(
    float* __restrict__ out,
    const float* __restrict__ b1, const float* __restrict__ br2,
    const float* __restrict__ b2, const float* __restrict__ b3,
    const float* __restrict__ br3,
    const float* __restrict__ Vth1, const float* __restrict__ tau1,
    const float* __restrict__ Vth2, const float* __restrict__ tau2,
    const float* __restrict__ Vth3, const float* __restrict__ tau3)
{
    extern __shared__ float dyn[];
    float* sWr2 = dyn;
    float* sW2  = dyn + MAT_F;
    float* sWr3 = dyn + 2 * MAT_F;
    float* Ws   = dyn + 3 * MAT_F;
    unsigned* smA = (unsigned*)(dyn + 3 * MAT_F + WS_F);
    unsigned* smB = smA + 512;
    unsigned* smC = smB + 512;

    const int tid = threadIdx.x;
    const int bt = blockIdx.x >> 4, ns = blockIdx.x & 15;
    const int b0 = bt * 32, n0 = ns * 32;
    const int bl = tid >> 4, nh = tid & 15, nn2 = nh * 2;
    const int b = b0 + bl, n = n0 + nn2;

    // resident weight slices
    for (int i = tid; i < 512 * 32; i += NTH) {
        int r = i >> 5, c = i & 31;
        sWr2[i] = g_Wr2t[(size_t)r * NN + n0 + c];
        sW2 [i] = g_W2t [(size_t)r * NN + n0 + c];
        sWr3[i] = g_Wr3t[(size_t)r * NN + n0 + c];
    }

    float ta1[2], ta2[2], ta3[2], vt1[2], vt2[2], vt3[2];
    float bb1[2], bb2[2], bb3[2], br2v[2], br3v[2];
    *(float2*)ta1 = *(const float2*)(tau1 + n); *(float2*)vt1 = *(const float2*)(Vth1 + n);
    *(float2*)ta2 = *(const float2*)(tau2 + n); *(float2*)vt2 = *(const float2*)(Vth2 + n);
    *(float2*)ta3 = *(const float2*)(tau3 + n); *(float2*)vt3 = *(const float2*)(Vth3 + n);
    *(float2*)bb1 = *(const float2*)(b1 + n);   *(float2*)bb2 = *(const float2*)(b2 + n);
    *(float2*)bb3 = *(const float2*)(b3 + n);
    *(float2*)br2v = *(const float2*)(br2 + n); *(float2*)br3v = *(const float2*)(br3 + n);

    float m1[2] = {}, m2[2] = {}, m3[2] = {};
    float s1[2] = {}, s2[2] = {}, s3[2] = {};
    float c1[2] = {}, c2[2] = {}, c3[2] = {};
    float r2[2], r3[2];
    __syncthreads();

    for (int t = 0; t < TT; ++t) {
        const int parw = t & 1, parr = parw ^ 1;

        // prefetch H1 (no spike dependency)
        const float2 h1v = *(const float2*)&g_H1[((size_t)t * BB + b) * NN + n];

        // masks from previous step: s1, s2 from parity buffers; s3 from history
        for (int i = tid; i < 512; i += NTH) {
            int gi = (b0 + (i >> 4)) * 16 + (i & 15);
            smA[i] = g_sp[0][parr][gi];
            smB[i] = g_sp[1][parr][gi];
            smC[i] = g_sp3[t][gi];
        }
        __syncthreads();

        // Phase 1: r1 = Wr2.s1p, r2 = Wr2.s2p (dual), r3 = Wr3.s3p (all resident)
        float r1[2] = {};
        r2[0] = r2[1] = 0.f;
        r3[0] = r3[1] = 0.f;
        gather_res2<true >(sWr2, smA, smB, bl, nn2, r1, r2);
        gather_res2<false>(sWr3, smC, smC, bl, nn2, r3, r3);

        float h[2];
        const float d1[2] = {h1v.x, h1v.y};
#pragma unroll
        for (int j = 0; j < 2; ++j)   // ((d1 + b1) + r1) + br2
            h[j] = __fadd_rn(__fadd_rn(__fadd_rn(d1[j], bb1[j]), r1[j]), br2v[j]);
        unsigned bits = lif2(m1, ta1, vt1, h, s1, c1);
        publish(&g_sp[0][parw][(b0 + bl) * 16 + ns], b0, bl, nh, bits);
        group_barrier(bt);

        // Phase 2: a2 = W2.s1(t) (resident)
        for (int i = tid; i < 512; i += NTH)
            smA[i] = g_sp[0][parw][(b0 + (i >> 4)) * 16 + (i & 15)];
        __syncthreads();
        float a2[2] = {};
        gather_res2<false>(sW2, smA, smA, bl, nn2, a2, a2);
#pragma unroll
        for (int j = 0; j < 2; ++j)
            h[j] = __fadd_rn(__fadd_rn(__fadd_rn(a2[j], bb2[j]), r2[j]), br2v[j]);
        bits = lif2(m2, ta2, vt2, h, s2, c2);
        publish(&g_sp[1][parw][(b0 + bl) * 16 + ns], b0, bl, nh, bits);
        group_barrier(bt);

        // Phase 3: a3 = W3.s2(t) (staged)
        for (int i = tid; i < 512; i += NTH)
            smB[i] = g_sp[1][parw][(b0 + (i >> 4)) * 16 + (i & 15)];
        __syncthreads();
        float a3[2] = {};
        gather_staged2(g_W3t, smB, Ws, bl, nn2, n0, tid, a3);
#pragma unroll
        for (int j = 0; j < 2; ++j)
            h[j] = __fadd_rn(__fadd_rn(__fadd_rn(a3[j], bb3[j]), r3[j]), br3v[j]);
        bits = lif2(m3, ta3, vt3, h, s3, c3);
        publish(&g_sp3[t + 1][(b0 + bl) * 16 + ns], b0, bl, nh, bits);
        group_barrier(bt);
    }

    // spike counts: sc1, sc2, sc3 appended after out[B][O][T]
    const float iT = 1.f / (float)TT;
    const size_t base = (size_t)BB * OO * TT, off = (size_t)b * NN + n;
    float2 v;
    v.x = __fmul_rn(c1[0], iT); v.y = __fmul_rn(c1[1], iT);
    *(float2*)&out[base + off] = v;
    v.x = __fmul_rn(c2[0], iT); v.y = __fmul_rn(c2[1], iT);
    *(float2*)&out[base + (size_t)BB * NN + off] = v;
    v.x = __fmul_rn(c3[0], iT); v.y = __fmul_rn(c3[1], iT);
    *(float2*)&out[base + 2 * (size_t)BB * NN + off] = v;
}

// out[b][o][t] = (ascending-k select chain of W4 over s3(t)) + b4[o]
// block: 32 lanes (20 active) x 8 timesteps; grid ((T+7)/8, B) with t<T guard
__global__ __launch_bounds__(256, 4) void out_kernel(
    float* __restrict__ out, const float* __restrict__ b4)
{
    __shared__ unsigned mk[8][16];
    const int lane = threadIdx.x & 31, tz = threadIdx.x >> 5;
    const int t = blockIdx.x * 8 + tz, b = blockIdx.y;
    if (t < TT && lane < 16) mk[tz][lane] = g_sp3[t + 1][b * 16 + lane];
    __syncthreads();
    if (t >= TT || lane >= OO) return;
    const int o = lane;
    float acc = 0.f;
#pragma unroll 1
    for (int w = 0; w < 16; ++w) {
        unsigned word = mk[tz][w];
#pragma unroll
        for (int j = 0; j < 32; ++j) {
            float sel = (word & (1u << j)) ? g_W4t[(w * 32 + j) * OO + o] : 0.f;
            acc = __fadd_rn(acc, sel);
        }
    }
    out[((size_t)b * OO + o) * TT + t] = __fadd_rn(acc, b4[o]);
}

extern "C" void kernel_launch(void* const* d_in, const int* in_sizes, int n_in,
                              void* d_out, int out_size)
{
    const float* x   = (const float*)d_in[0];
    const float* W1  = (const float*)d_in[1];
    const float* b1  = (const float*)d_in[2];
    const float* W2  = (const float*)d_in[3];
    const float* b2  = (const float*)d_in[4];
    const float* Wr2 = (const float*)d_in[5];
    const float* br2 = (const float*)d_in[6];
    const float* W3  = (const float*)d_in[7];
    const float* b3  = (const float*)d_in[8];
    const float* Wr3 = (const float*)d_in[9];
    const float* br3 = (const float*)d_in[10];
    const float* W4  = (const float*)d_in[11];
    const float* b4  = (const float*)d_in[12];
    const float* Vth1 = (const float*)d_in[13];
    const float* tau1 = (const float*)d_in[14];
    const float* Vth2 = (const float*)d_in[15];
    const float* tau2 = (const float*)d_in[16];
    const float* Vth3 = (const float*)d_in[17];
    const float* tau3 = (const float*)d_in[18];
    float* out = (float*)d_out;

    cudaFuncSetAttribute(rsnn_recurrent_kernel,
                         cudaFuncAttributeMaxDynamicSharedMemorySize, SMEM_BYTES);

    prep_kernel<<<256, 256>>>(W1, W2, Wr2, W3, Wr3, W4);
    dim3 g(NN / 128, 4, BB);
    h1_gemm_kernel<<<g, 256>>>(x);
    rsnn_recurrent_kernel<<<NCTAS, NTH, SMEM_BYTES>>>(
        out, b1, br2, b2, b3, br3, Vth1, tau1, Vth2, tau2, Vth3, tau3);
    dim3 go((TT + 7) / 8, BB);
    out_kernel<<<go, 256>>>(out, b4);
}

// round 13
// speedup vs baseline: 1.4989x; 1.0057x over previous
#include <cuda_runtime.h>

#define BB 256
#define CC 700
#define TT 500
#define NN 512
#define OO 20
#define CP 704
#define NCTAS 128
#define NTH 512
#define NGRP 8
#define GSZ 16

// dyn smem: sWr2[512*32], sW2[512*32], sWr3[512*32], Ws[128*32] (floats),
// then smA/B/C[512] (unsigned)
#define MAT_F (512 * 32)
#define WS_F (128 * 32)
#define SMEM_BYTES ((3 * MAT_F + WS_F) * 4 + 3 * 512 * 4)

__device__ float g_W1t[(size_t)CP * NN];
__device__ float g_Wr2t[(size_t)NN * NN];
__device__ float g_W2t[(size_t)NN * NN];
__device__ float g_W3t[(size_t)NN * NN];
__device__ float g_Wr3t[(size_t)NN * NN];
__device__ float g_W4t[(size_t)NN * OO];
__device__ float g_H1[(size_t)TT * BB * NN];
__device__ unsigned g_sp[2][2][BB * 16];          // s1, s2 (double-buffered)
__device__ unsigned g_sp3[TT + 1][BB * 16];       // s3 per timestep (for out kernel)
__device__ unsigned g_gcnt[NGRP * 32];            // 128B-padded per-group counters
__device__ unsigned g_gphz[NGRP * 32];            // per-group epoch

// Scoped-atomic group barrier: release-arrive, acquire-spin on epoch.
// No __threadfence (no CCTL.IVALL / L1 flush) — cross-CTA data is read with
// __ldcg (L2-coherent) so L1 invalidation is not needed for correctness.
__device__ __forceinline__ void group_barrier(int bt, unsigned epoch) {
    __syncthreads();
    if (threadIdx.x == 0) {
        unsigned* cnt = &g_gcnt[bt * 32];
        unsigned* phz = &g_gphz[bt * 32];
        unsigned old;
        asm volatile("atom.add.release.gpu.global.u32 %0,[%1],%2;"
                     : "=r"(old) : "l"(cnt), "r"(1u) : "memory");
        if (old == GSZ - 1) {
            *cnt = 0u;   // ordered before the release store below
            asm volatile("st.release.gpu.global.u32 [%0],%1;"
                         :: "l"(phz), "r"(epoch) : "memory");
        } else {
            unsigned v;
            do {
                __nanosleep(20);
                asm volatile("ld.acquire.gpu.global.u32 %0,[%1];"
                             : "=r"(v) : "l"(phz) : "memory");
            } while (v < epoch);
        }
    }
    __syncthreads();
}

__global__ void prep_kernel(
    const float* __restrict__ W1, const float* __restrict__ W2,
    const float* __restrict__ Wr2, const float* __restrict__ W3,
    const float* __restrict__ Wr3, const float* __restrict__ W4)
{
    const int tid = blockIdx.x * blockDim.x + threadIdx.x;
    const int str = gridDim.x * blockDim.x;
    for (int i = tid; i < CP * NN; i += str) {
        int c = i >> 9, n = i & 511;
        g_W1t[i] = (c < CC) ? W1[(size_t)n * CC + c] : 0.f;
    }
    for (int i = tid; i < NN * NN; i += str) {
        int k = i >> 9, n = i & 511;
        size_t j = (size_t)n * NN + k;
        g_Wr2t[i] = Wr2[j]; g_W2t[i] = W2[j]; g_W3t[i] = W3[j]; g_Wr3t[i] = Wr3[j];
    }
    for (int i = tid; i < NN * OO; i += str)
        g_W4t[i] = W4[(size_t)(i % OO) * NN + (i / OO)];
    for (int i = tid; i < 2 * 2 * BB * 16; i += str) (&g_sp[0][0][0])[i] = 0u;
    for (int i = tid; i < BB * 16; i += str) g_sp3[0][i] = 0u;   // s3(-1) = 0
    for (int i = tid; i < NGRP * 32; i += str) { g_gcnt[i] = 0u; g_gphz[i] = 0u; }
}

// H1[t][b][n] = sum_c x[b][c][t] * W1[n][c]  (ascending-c FFMA chain)
__global__ __launch_bounds__(256, 2) void h1_gemm_kernel(const float* __restrict__ x)
{
    __shared__ float As[8][128], Bs[8][128];
    const int n0 = blockIdx.x * 128, t0 = blockIdx.y * 128, b = blockIdx.z;
    const int tx = threadIdx.x & 15, ty = threadIdx.x >> 4;
    const float* __restrict__ xb = x + (size_t)b * CC * TT;
    float acc[8][8] = {};
    float ra[4], rb[4];

#define H1_LOAD(c0)                                                          \
    _Pragma("unroll")                                                        \
    for (int u = 0; u < 4; ++u) {                                            \
        int i = threadIdx.x + u * 256, kc = i >> 7, e = i & 127;             \
        int c = (c0) + kc, t = t0 + e;                                       \
        ra[u] = (c < CC && t < TT) ? xb[(size_t)c * TT + t] : 0.f;           \
        rb[u] = g_W1t[(size_t)c * NN + n0 + e];                              \
    }

    H1_LOAD(0)
    for (int c0 = 0; c0 < CP; c0 += 8) {
#pragma unroll
        for (int u = 0; u < 4; ++u) {
            int i = threadIdx.x + u * 256;
            As[i >> 7][i & 127] = ra[u];
            Bs[i >> 7][i & 127] = rb[u];
        }
        __syncthreads();
        if (c0 + 8 < CP) { H1_LOAD(c0 + 8) }
#pragma unroll
        for (int kc = 0; kc < 8; ++kc) {
            float av[8], bv[8];
            *(float4*)av       = *(const float4*)&As[kc][ty * 8];
            *(float4*)(av + 4) = *(const float4*)&As[kc][ty * 8 + 4];
            *(float4*)bv       = *(const float4*)&Bs[kc][tx * 8];
            *(float4*)(bv + 4) = *(const float4*)&Bs[kc][tx * 8 + 4];
#pragma unroll
            for (int i = 0; i < 8; ++i)
#pragma unroll
                for (int j = 0; j < 8; ++j)
                    acc[i][j] = __fmaf_rn(av[i], bv[j], acc[i][j]);
        }
        __syncthreads();
    }
#pragma unroll
    for (int i = 0; i < 8; ++i) {
        int t = t0 + ty * 8 + i;
        if (t < TT) {
            float* dst = &g_H1[((size_t)t * BB + b) * NN + n0 + tx * 8];
            *(float4*)dst       = *(float4*)&acc[i][0];
            *(float4*)(dst + 4) = *(float4*)&acc[i][4];
        }
    }
}

// one mask word, software-pipelined depth 2 (load next bit while adding current);
// adds stay in strictly ascending bit order -> bit-exact vs reference chain
__device__ __forceinline__ void bits_pipelined(const float* __restrict__ base,
                                               unsigned m, float* a)
{
    if (!m) return;
    int j = __ffs(m) - 1; m &= m - 1u;
    float2 cur = *(const float2*)(base + j * 32);
    while (m) {
        int j2 = __ffs(m) - 1; m &= m - 1u;
        float2 nxt = *(const float2*)(base + j2 * 32);
        a[0] = __fadd_rn(a[0], cur.x); a[1] = __fadd_rn(a[1], cur.y);
        cur = nxt;
    }
    a[0] = __fadd_rn(a[0], cur.x); a[1] = __fadd_rn(a[1], cur.y);
}

// resident gather, 2-wide per thread (float2), ascending k; optional dual mask
template <bool DUAL>
__device__ __forceinline__ void gather_res2(
    const float* __restrict__ sW, const unsigned* __restrict__ smX,
    const unsigned* __restrict__ smY, int bl, int nn2, float* aX, float* aY)
{
#pragma unroll 1
    for (int w = 0; w < 16; ++w) {
        const float* base = sW + (w * 32) * 32 + nn2;
        bits_pipelined(base, smX[bl * 16 + w], aX);
        if (DUAL) bits_pipelined(base, smY[bl * 16 + w], aY);
    }
}

// staged gather (W3 streamed through Ws in 128-k chunks), 2-wide, ascending k
__device__ __forceinline__ void gather_staged2(
    const float* __restrict__ Wt, const unsigned* __restrict__ smX,
    float* __restrict__ Ws, int bl, int nn2, int n0, int tid, float* aX)
{
#pragma unroll 1
    for (int kc = 0; kc < 4; ++kc) {
        const float* __restrict__ src = Wt + (size_t)(kc * 128) * NN + n0;
#pragma unroll
        for (int u = 0; u < 2; ++u) {
            int idx = tid + u * NTH;                     // float4 index, 1024 total
            int row = idx >> 3, c4 = idx & 7;
            ((float4*)Ws)[idx] = __ldcg((const float4*)(src + (size_t)row * NN + c4 * 4));
        }
        __syncthreads();
#pragma unroll
        for (int w = 0; w < 4; ++w)
            bits_pipelined(Ws + (w * 32) * 32 + nn2, smX[bl * 16 + kc * 4 + w], aX);
        __syncthreads();
    }
}

// LIF over 2 components: m = ((tau*m)*(1-s))+h, separate roundings
__device__ __forceinline__ unsigned lif2(float* m, const float* tau, const float* vth,
                                         const float* h, float* s, float* cnt)
{
    unsigned bits = 0u;
#pragma unroll
    for (int j = 0; j < 2; ++j) {
        float one_ms = __fadd_rn(1.f, -s[j]);
        m[j] = __fadd_rn(__fmul_rn(__fmul_rn(tau[j], m[j]), one_ms), h[j]);
        float sp = (__fadd_rn(m[j], -vth[j]) > 0.f) ? 1.f : 0.f;
        cnt[j] += sp; s[j] = sp;
        bits |= ((unsigned)sp) << j;
    }
    return bits;
}

// pack 16 threads x 2 bits -> 32-bit row word via shuffle-OR (stays in half-warp)
__device__ __forceinline__ void publish(unsigned* dst, int nh, unsigned bits)
{
    unsigned word = bits << (nh * 2);
    word |= __shfl_xor_sync(0xffffffffu, word, 1);
    word |= __shfl_xor_sync(0xffffffffu, word, 2);
    word |= __shfl_xor_sync(0xffffffffu, word, 4);
    word |= __shfl_xor_sync(0xffffffffu, word, 8);
    if (nh == 0) *dst = word;
}

__global__ __launch_bounds__(NTH, 1) void rsnn_recurrent_kernel(
    float* __restrict__ out,
    const float* __restrict__ b1, const float* __restrict__ br2,
    const float* __restrict__ b2, const float* __restrict__ b3,
    const float* __restrict__ br3,
    const float* __restrict__ Vth1, const float* __restrict__ tau1,
    const float* __restrict__ Vth2, const float* __restrict__ tau2,
    const float* __restrict__ Vth3, const float* __restrict__ tau3)
{
    extern __shared__ float dyn[];
    float* sWr2 = dyn;
    float* sW2  = dyn + MAT_F;
    float* sWr3 = dyn + 2 * MAT_F;
    float* Ws   = dyn + 3 * MAT_F;
    unsigned* smA = (unsigned*)(dyn + 3 * MAT_F + WS_F);
    unsigned* smB = smA + 512;
    unsigned* smC = smB + 512;

    const int tid = threadIdx.x;
    const int bt = blockIdx.x >> 4, ns = blockIdx.x & 15;
    const int b0 = bt * 32, n0 = ns * 32;
    const int bl = tid >> 4, nh = tid & 15, nn2 = nh * 2;
    const int b = b0 + bl, n = n0 + nn2;

    // resident weight slices
    for (int i = tid; i < 512 * 32; i += NTH) {
        int r = i >> 5, c = i & 31;
        sWr2[i] = g_Wr2t[(size_t)r * NN + n0 + c];
        sW2 [i] = g_W2t [(size_t)r * NN + n0 + c];
        sWr3[i] = g_Wr3t[(size_t)r * NN + n0 + c];
    }

    float ta1[2], ta2[2], ta3[2], vt1[2], vt2[2], vt3[2];
    float bb1[2], bb2[2], bb3[2], br2v[2], br3v[2];
    *(float2*)ta1 = *(const float2*)(tau1 + n); *(float2*)vt1 = *(const float2*)(Vth1 + n);
    *(float2*)ta2 = *(const float2*)(tau2 + n); *(float2*)vt2 = *(const float2*)(Vth2 + n);
    *(float2*)ta3 = *(const float2*)(tau3 + n); *(float2*)vt3 = *(const float2*)(Vth3 + n);
    *(float2*)bb1 = *(const float2*)(b1 + n);   *(float2*)bb2 = *(const float2*)(b2 + n);
    *(float2*)bb3 = *(const float2*)(b3 + n);
    *(float2*)br2v = *(const float2*)(br2 + n); *(float2*)br3v = *(const float2*)(br3 + n);

    float m1[2] = {}, m2[2] = {}, m3[2] = {};
    float s1[2] = {}, s2[2] = {}, s3[2] = {};
    float c1[2] = {}, c2[2] = {}, c3[2] = {};
    float r2[2], r3[2];
    __syncthreads();

    for (int t = 0; t < TT; ++t) {
        const int parw = t & 1, parr = parw ^ 1;

        // prefetch H1 (no spike dependency); __ldcg: read-once, L2-coherent
        const float2 h1v = __ldcg((const float2*)&g_H1[((size_t)t * BB + b) * NN + n]);

        // masks from previous step: s1, s2 from parity buffers; s3 from history
        for (int i = tid; i < 512; i += NTH) {
            int gi = (b0 + (i >> 4)) * 16 + (i & 15);
            smA[i] = __ldcg(&g_sp[0][parr][gi]);
            smB[i] = __ldcg(&g_sp[1][parr][gi]);
            smC[i] = __ldcg(&g_sp3[t][gi]);
        }
        __syncthreads();

        // Phase 1: r1 = Wr2.s1p, r2 = Wr2.s2p (dual), r3 = Wr3.s3p (all resident)
        float r1[2] = {};
        r2[0] = r2[1] = 0.f;
        r3[0] = r3[1] = 0.f;
        gather_res2<true >(sWr2, smA, smB, bl, nn2, r1, r2);
        gather_res2<false>(sWr3, smC, smC, bl, nn2, r3, r3);

        float h[2];
        const float d1[2] = {h1v.x, h1v.y};
#pragma unroll
        for (int j = 0; j < 2; ++j)   // ((d1 + b1) + r1) + br2
            h[j] = __fadd_rn(__fadd_rn(__fadd_rn(d1[j], bb1[j]), r1[j]), br2v[j]);
        unsigned bits = lif2(m1, ta1, vt1, h, s1, c1);
        publish(&g_sp[0][parw][(b0 + bl) * 16 + ns], nh, bits);
        group_barrier(bt, 3u * t + 1u);

        // Phase 2: a2 = W2.s1(t) (resident)
        for (int i = tid; i < 512; i += NTH)
            smA[i] = __ldcg(&g_sp[0][parw][(b0 + (i >> 4)) * 16 + (i & 15)]);
        __syncthreads();
        float a2[2] = {};
        gather_res2<false>(sW2, smA, smA, bl, nn2, a2, a2);
#pragma unroll
        for (int j = 0; j < 2; ++j)
            h[j] = __fadd_rn(__fadd_rn(__fadd_rn(a2[j], bb2[j]), r2[j]), br2v[j]);
        bits = lif2(m2, ta2, vt2, h, s2, c2);
        publish(&g_sp[1][parw][(b0 + bl) * 16 + ns], nh, bits);
        group_barrier(bt, 3u * t + 2u);

        // Phase 3: a3 = W3.s2(t) (staged)
        for (int i = tid; i < 512; i += NTH)
            smB[i] = __ldcg(&g_sp[1][parw][(b0 + (i >> 4)) * 16 + (i & 15)]);
        __syncthreads();
        float a3[2] = {};
        gather_staged2(g_W3t, smB, Ws, bl, nn2, n0, tid, a3);
#pragma unroll
        for (int j = 0; j < 2; ++j)
            h[j] = __fadd_rn(__fadd_rn(__fadd_rn(a3[j], bb3[j]), r3[j]), br3v[j]);
        bits = lif2(m3, ta3, vt3, h, s3, c3);
        publish(&g_sp3[t + 1][(b0 + bl) * 16 + ns], nh, bits);
        group_barrier(bt, 3u * t + 3u);
    }

    // spike counts: sc1, sc2, sc3 appended after out[B][O][T]
    const float iT = 1.f / (float)TT;
    const size_t base = (size_t)BB * OO * TT, off = (size_t)b * NN + n;
    float2 v;
    v.x = __fmul_rn(c1[0], iT); v.y = __fmul_rn(c1[1], iT);
    *(float2*)&out[base + off] = v;
    v.x = __fmul_rn(c2[0], iT); v.y = __fmul_rn(c2[1], iT);
    *(float2*)&out[base + (size_t)BB * NN + off] = v;
    v.x = __fmul_rn(c3[0], iT); v.y = __fmul_rn(c3[1], iT);
    *(float2*)&out[base + 2 * (size_t)BB * NN + off] = v;
}

// out[b][o][t] = (ascending-k select chain of W4 over s3(t)) + b4[o]
// block: 32 lanes (20 active) x 8 timesteps; grid ((T+7)/8, B) with t<T guard
__global__ __launch_bounds__(256, 4) void out_kernel(
    float* __restrict__ out, const float* __restrict__ b4)
{
    __shared__ unsigned mk[8][16];
    const int lane = threadIdx.x & 31, tz = threadIdx.x >> 5;
    const int t = blockIdx.x * 8 + tz, b = blockIdx.y;
    if (t < TT && lane < 16) mk[tz][lane] = g_sp3[t + 1][b * 16 + lane];
    __syncthreads();
    if (t >= TT || lane >= OO) return;
    const int o = lane;
    float acc = 0.f;
#pragma unroll 1
    for (int w = 0; w < 16; ++w) {
        unsigned word = mk[tz][w];
#pragma unroll
        for (int j = 0; j < 32; ++j) {
            float sel = (word & (1u << j)) ? g_W4t[(w * 32 + j) * OO + o] : 0.f;
            acc = __fadd_rn(acc, sel);
        }
    }
    out[((size_t)b * OO + o) * TT + t] = __fadd_rn(acc, b4[o]);
}

extern "C" void kernel_launch(void* const* d_in, const int* in_sizes, int n_in,
                              void* d_out, int out_size)
{
    const float* x   = (const float*)d_in[0];
    const float* W1  = (const float*)d_in[1];
    const float* b1  = (const float*)d_in[2];
    const float* W2  = (const float*)d_in[3];
    const float* b2  = (const float*)d_in[4];
    const float* Wr2 = (const float*)d_in[5];
    const float* br2 = (const float*)d_in[6];
    const float* W3  = (const float*)d_in[7];
    const float* b3  = (const float*)d_in[8];
    const float* Wr3 = (const float*)d_in[9];
    const float* br3 = (const float*)d_in[10];
    const float* W4  = (const float*)d_in[11];
    const float* b4  = (const float*)d_in[12];
    const float* Vth1 = (const float*)d_in[13];
    const float* tau1 = (const float*)d_in[14];
    const float* Vth2 = (const float*)d_in[15];
    const float* tau2 = (const float*)d_in[16];
    const float* Vth3 = (const float*)d_in[17];
    const float* tau3 = (const float*)d_in[18];
    float* out = (float*)d_out;

    cudaFuncSetAttribute(rsnn_recurrent_kernel,
                         cudaFuncAttributeMaxDynamicSharedMemorySize, SMEM_BYTES);

    prep_kernel<<<256, 256>>>(W1, W2, Wr2, W3, Wr3, W4);
    dim3 g(NN / 128, 4, BB);
    h1_gemm_kernel<<<g, 256>>>(x);
    rsnn_recurrent_kernel<<<NCTAS, NTH, SMEM_BYTES>>>(
        out, b1, br2, b2, b3, br3, Vth1, tau1, Vth2, tau2, Vth3, tau3);
    dim3 go((TT + 7) / 8, BB);
    out_kernel<<<go, 256>>>(out, b4);
}